// round 3
// baseline (speedup 1.0000x reference)
#include <cuda_runtime.h>

#define NHX 64
#define NHY 64
#define NU  512
#define NV  512
#define LCH 16
#define NPLANES 6

#define CAPN 1000000
#define TILE_SHIFT 3                         // 8x8 uv cells per tile
#define NBUCKETS (8 * 64 * 64)               // m x utile x vtile = 32768

__device__ int    g_count[NBUCKETS];         // zero-initialized at load; scan re-zeroes
__device__ int    g_ptr[NBUCKETS];
__device__ float4 g_rec[CAPN];               // {hx, hy, u, v} sorted
__device__ int    g_idx[CAPN];               // pt | (m << 24)

// ---------------- sort pipeline ----------------

__device__ __forceinline__ int bucket_of(int mi, float uu, float vv) {
    int uc = (int)(uu * (float)NU); if (uc > NU - 1) uc = NU - 1;
    int vc = (int)(vv * (float)NV); if (vc > NV - 1) vc = NV - 1;
    return (mi << 12) | ((uc >> TILE_SHIFT) << 6) | (vc >> TILE_SHIFT);
}

// 4 points per thread for MLP on the atomics
__global__ void __launch_bounds__(256)
hist_kernel(const int* __restrict__ m,
            const float* __restrict__ u,
            const float* __restrict__ v, int N) {
    int base = (blockIdx.x * blockDim.x + threadIdx.x) * 4;
#pragma unroll
    for (int k = 0; k < 4; k++) {
        int pt = base + k;
        if (pt < N) atomicAdd(&g_count[bucket_of(m[pt], u[pt], v[pt])], 1);
    }
}

// single block 1024 threads, 32 buckets each; also re-zeroes g_count for next call
__global__ void scan_kernel() {
    __shared__ int sh[1024];
    int t = threadIdx.x;
    int base = t * 32;
    int c[32];
    int s = 0;
#pragma unroll
    for (int i = 0; i < 32; i++) { c[i] = g_count[base + i]; s += c[i]; }
    sh[t] = s;
    __syncthreads();
    for (int off = 1; off < 1024; off <<= 1) {
        int val = (t >= off) ? sh[t - off] : 0;
        __syncthreads();
        sh[t] += val;
        __syncthreads();
    }
    int ex = sh[t] - s;
#pragma unroll
    for (int i = 0; i < 32; i++) {
        g_ptr[base + i] = ex;
        ex += c[i];
        g_count[base + i] = 0;     // restore invariant for next kernel_launch
    }
}

__global__ void __launch_bounds__(256)
scatter_kernel(const int* __restrict__ m,
               const float* __restrict__ h,
               const float* __restrict__ u,
               const float* __restrict__ v, int N) {
    int base = (blockIdx.x * blockDim.x + threadIdx.x) * 4;
    int   mi[4]; float uu[4], vv[4], hx[4], hy[4]; int pos[4]; bool ok[4];
#pragma unroll
    for (int k = 0; k < 4; k++) {
        int pt = base + k;
        ok[k] = (pt < N);
        if (ok[k]) {
            mi[k] = m[pt]; uu[k] = u[pt]; vv[k] = v[pt];
            hx[k] = h[2 * pt]; hy[k] = h[2 * pt + 1];
        }
    }
#pragma unroll
    for (int k = 0; k < 4; k++)
        if (ok[k]) pos[k] = atomicAdd(&g_ptr[bucket_of(mi[k], uu[k], vv[k])], 1);
#pragma unroll
    for (int k = 0; k < 4; k++)
        if (ok[k]) {
            __stcs(&g_rec[pos[k]], make_float4(hx[k], hy[k], uu[k], vv[k]));
            __stcs(&g_idx[pos[k]], (base + k) | (mi[k] << 24));
        }
}

// ---------------- interpolation ----------------

__device__ __forceinline__ void axis(float ind, int I, int& i1, int& i2, float& fr) {
    if (ind == (float)I) ind = (float)(I - 1);
    i1 = (int)ind;
    fr = ind - (float)i1;
    i2 = i1 + 1;
    if (i2 == I) i2 = 0;
}

__device__ __forceinline__ float4 bilerp4(const float* __restrict__ F,
                                          int mi, int I, int J,
                                          int i1, int i2, float ir,
                                          int j1, int j2, float jr, int q) {
    int rowA = (mi * I + i1) * J;
    int rowB = (mi * I + i2) * J;
    const float4* p11 = reinterpret_cast<const float4*>(F + (size_t)(rowA + j1) * LCH) + q;
    const float4* p21 = reinterpret_cast<const float4*>(F + (size_t)(rowB + j1) * LCH) + q;
    const float4* p12 = reinterpret_cast<const float4*>(F + (size_t)(rowA + j2) * LCH) + q;
    const float4* p22 = reinterpret_cast<const float4*>(F + (size_t)(rowB + j2) * LCH) + q;
    float4 a = __ldg(p11);
    float4 b = __ldg(p21);
    float4 c = __ldg(p12);
    float4 d = __ldg(p22);
    float omi = 1.0f - ir, omj = 1.0f - jr;
    float4 out;
    out.x = (a.x * omi + b.x * ir) * omj + (c.x * omi + d.x * ir) * jr;
    out.y = (a.y * omi + b.y * ir) * omj + (c.y * omi + d.y * ir) * jr;
    out.z = (a.z * omi + b.z * ir) * omj + (c.z * omi + d.z * ir) * jr;
    out.w = (a.w * omi + b.w * ir) * omj + (c.w * omi + d.w * ir) * jr;
    return out;
}

__global__ void __launch_bounds__(256)
triplane_sorted_kernel(const float* __restrict__ Fxy,
                       const float* __restrict__ Fxu,
                       const float* __restrict__ Fxv,
                       const float* __restrict__ Fyu,
                       const float* __restrict__ Fyv,
                       const float* __restrict__ Fuv,
                       float4*      __restrict__ out,
                       int N) {
    int gid = blockIdx.x * blockDim.x + threadIdx.x;
    int p   = gid >> 2;
    int q   = gid & 3;
    if (p >= N) return;

    float4 rec = __ldcs(&g_rec[p]);         // one-touch stream: don't pollute L2
    int packed  = __ldcs(&g_idx[p]);
    int pt = packed & 0x00FFFFFF;
    int mi = packed >> 24;

    float ind_hx = (rec.x + 1.0f) / 2.0f * (float)NHX;
    float ind_hy = (rec.y + 1.0f) / 2.0f * (float)NHY;
    float ind_u  = rec.z * (float)NU;
    float ind_v  = rec.w * (float)NV;

    int x1, x2, y1, y2, u1, u2, v1, v2;
    float xr, yr, ur, vr;
    axis(ind_hx, NHX, x1, x2, xr);
    axis(ind_hy, NHY, y1, y2, yr);
    axis(ind_u,  NU,  u1, u2, ur);
    axis(ind_v,  NV,  v1, v2, vr);

    float4* o = out + (size_t)pt * (NPLANES * (LCH / 4));

    // streaming stores: keep L2 for the factor planes
    __stcs(&o[0 * 4 + q], bilerp4(Fxy, mi, NHX, NHY, x1, x2, xr, y1, y2, yr, q));
    __stcs(&o[1 * 4 + q], bilerp4(Fxu, mi, NHX, NU,  x1, x2, xr, u1, u2, ur, q));
    __stcs(&o[2 * 4 + q], bilerp4(Fxv, mi, NHX, NV,  x1, x2, xr, v1, v2, vr, q));
    __stcs(&o[3 * 4 + q], bilerp4(Fyu, mi, NHY, NU,  y1, y2, yr, u1, u2, ur, q));
    __stcs(&o[4 * 4 + q], bilerp4(Fyv, mi, NHY, NV,  y1, y2, yr, v1, v2, vr, q));
    __stcs(&o[5 * 4 + q], bilerp4(Fuv, mi, NU,  NV,  u1, u2, ur, v1, v2, vr, q));
}

// Fallback if N exceeds static scratch
__global__ void __launch_bounds__(256)
triplane_direct_kernel(const int*   __restrict__ m,
                       const float* __restrict__ h,
                       const float* __restrict__ u,
                       const float* __restrict__ v,
                       const float* __restrict__ Fxy,
                       const float* __restrict__ Fxu,
                       const float* __restrict__ Fxv,
                       const float* __restrict__ Fyu,
                       const float* __restrict__ Fyv,
                       const float* __restrict__ Fuv,
                       float4*      __restrict__ out,
                       int N) {
    int gid = blockIdx.x * blockDim.x + threadIdx.x;
    int pt  = gid >> 2;
    int q   = gid & 3;
    if (pt >= N) return;

    int   mi = m[pt];
    float ind_hx = (h[2 * pt] + 1.0f) / 2.0f * (float)NHX;
    float ind_hy = (h[2 * pt + 1] + 1.0f) / 2.0f * (float)NHY;
    float ind_u  = u[pt] * (float)NU;
    float ind_v  = v[pt] * (float)NV;

    int x1, x2, y1, y2, u1, u2, v1, v2;
    float xr, yr, ur, vr;
    axis(ind_hx, NHX, x1, x2, xr);
    axis(ind_hy, NHY, y1, y2, yr);
    axis(ind_u,  NU,  u1, u2, ur);
    axis(ind_v,  NV,  v1, v2, vr);

    float4* o = out + (size_t)pt * (NPLANES * (LCH / 4));
    __stcs(&o[0 * 4 + q], bilerp4(Fxy, mi, NHX, NHY, x1, x2, xr, y1, y2, yr, q));
    __stcs(&o[1 * 4 + q], bilerp4(Fxu, mi, NHX, NU,  x1, x2, xr, u1, u2, ur, q));
    __stcs(&o[2 * 4 + q], bilerp4(Fxv, mi, NHX, NV,  x1, x2, xr, v1, v2, vr, q));
    __stcs(&o[3 * 4 + q], bilerp4(Fyu, mi, NHY, NU,  y1, y2, yr, u1, u2, ur, q));
    __stcs(&o[4 * 4 + q], bilerp4(Fyv, mi, NHY, NV,  y1, y2, yr, v1, v2, vr, q));
    __stcs(&o[5 * 4 + q], bilerp4(Fuv, mi, NU,  NV,  u1, u2, ur, v1, v2, vr, q));
}

extern "C" void kernel_launch(void* const* d_in, const int* in_sizes, int n_in,
                              void* d_out, int out_size) {
    // order: r, m, h, u, v, Fxy, Fxu, Fxv, Fyu, Fyv, Fuv   (r unused)
    const int*   m   = (const int*)  d_in[1];
    const float* h   = (const float*)d_in[2];
    const float* u   = (const float*)d_in[3];
    const float* v   = (const float*)d_in[4];
    const float* Fxy = (const float*)d_in[5];
    const float* Fxu = (const float*)d_in[6];
    const float* Fxv = (const float*)d_in[7];
    const float* Fyu = (const float*)d_in[8];
    const float* Fyv = (const float*)d_in[9];
    const float* Fuv = (const float*)d_in[10];

    int N = in_sizes[1];

    if (N <= CAPN) {
        int tpb = 256;
        int pts4 = (N + 3) / 4;
        hist_kernel<<<(pts4 + tpb - 1) / tpb, tpb>>>(m, u, v, N);
        scan_kernel<<<1, 1024>>>();
        scatter_kernel<<<(pts4 + tpb - 1) / tpb, tpb>>>(m, h, u, v, N);

        long long tt = (long long)N * 4;
        triplane_sorted_kernel<<<(int)((tt + tpb - 1) / tpb), tpb>>>(
            Fxy, Fxu, Fxv, Fyu, Fyv, Fuv, (float4*)d_out, N);
    } else {
        long long tt = (long long)N * 4;
        int tpb = 256;
        triplane_direct_kernel<<<(int)((tt + tpb - 1) / tpb), tpb>>>(
            m, h, u, v, Fxy, Fxu, Fxv, Fyu, Fyv, Fuv, (float4*)d_out, N);
    }
}